// round 13
// baseline (speedup 1.0000x reference)
#include <cuda_runtime.h>
#include <cuda_bf16.h>
#include <math.h>
#include <stdint.h>
#include <float.h>

#define N_RULES 50000
#define N_PAD   50176            // 392 * 128
#define D_DIM   384
#define B_ROWS  8192
#define H_DIM   256
#define TOPK    8
#define SLOTS   4
#define NCAND   (SLOTS * TOPK)   // 32

#define BM 128
#define BN 128
#define BK 64
#define KCH 6                    // 384 / 64
#define GTILES 392               // rule tiles per group
#define NGROUP 64                // row groups
#define NUNITS (NGROUP * GTILES) // 25088
#define NCTAS  148
#define ASTRIDE 392              // elems: 384 + 8 (784B row, LDSM conflict-free)
#define BSTRIDE 72               // elems: 64 + 8  (144B row)
#define NTHREADS 512

// ---------------- device scratch ----------------
__device__ __nv_bfloat16 g_rb[(size_t)N_PAD * D_DIM];
__device__ float  g_rinv[N_PAD];
__device__ __nv_bfloat16 g_qb[(size_t)B_ROWS * D_DIM];
__device__ float  g_topv[(size_t)B_ROWS * NCAND];
__device__ int    g_topi[(size_t)B_ROWS * NCAND];

// unit range helpers: ustart(c) = c*6272/37  (25088/148 = 6272/37)
__device__ __forceinline__ int ustart(int c) { return (c * 6272) / 37; }

// ---------------- smem struct ----------------
struct __align__(16) SimsSmem {
    __nv_bfloat16 As[BM * ASTRIDE];     // 100352 B
    __nv_bfloat16 Bs[3][BN * BSTRIDE];  // 55296 B
    float topv[BM * TOPK];              // 4096 B
    int   topi[BM * TOPK];              // 4096 B
    float thr[BM];                      // 512 B
    int   lck[BM];                      // 512 B
};                                      // 164864 B

// ---------------- PTX helpers ----------------
__device__ __forceinline__ uint32_t smem_u32(const void* p) {
    uint32_t a;
    asm("{ .reg .u64 t; cvta.to.shared.u64 t, %1; cvt.u32.u64 %0, t; }" : "=r"(a) : "l"(p));
    return a;
}
__device__ __forceinline__ void cp16(uint32_t dst, const void* src) {
    asm volatile("cp.async.cg.shared.global [%0], [%1], 16;" :: "r"(dst), "l"(src));
}
__device__ __forceinline__ void ldsm_x4(uint32_t* r, uint32_t addr) {
    asm volatile("ldmatrix.sync.aligned.m8n8.x4.shared.b16 {%0,%1,%2,%3}, [%4];"
                 : "=r"(r[0]), "=r"(r[1]), "=r"(r[2]), "=r"(r[3]) : "r"(addr));
}
__device__ __forceinline__ void mma16816(float* c, const uint32_t* a,
                                         uint32_t b0, uint32_t b1) {
    asm volatile(
        "mma.sync.aligned.m16n8k16.row.col.f32.bf16.bf16.f32 "
        "{%0,%1,%2,%3}, {%4,%5,%6,%7}, {%8,%9}, {%0,%1,%2,%3};\n"
        : "+f"(c[0]), "+f"(c[1]), "+f"(c[2]), "+f"(c[3])
        : "r"(a[0]), "r"(a[1]), "r"(a[2]), "r"(a[3]), "r"(b0), "r"(b1));
}

// ---------------- candidate init ----------------
__global__ void init_cand_kernel() {
    size_t i = (size_t)blockIdx.x * 256 + threadIdx.x;   // 262144 total
    g_topv[i] = -FLT_MAX;
    g_topi[i] = 0;
}

// ---------------- fused prep: warp-per-row normalize + bf16 cast ------------
__global__ __launch_bounds__(256)
void prep_all_kernel(const float* __restrict__ rules, const float* __restrict__ emb) {
    const int warp = threadIdx.x >> 5;
    const int lane = threadIdx.x & 31;
    const int row  = blockIdx.x * 8 + warp;

    const float* src;
    __nv_bfloat162* dst;
    bool is_rule = (row < N_PAD);
    if (is_rule) {
        if (row >= N_RULES) {   // pad rows: zero
            __nv_bfloat162 z = __float22bfloat162_rn(make_float2(0.f, 0.f));
            __nv_bfloat162* d = reinterpret_cast<__nv_bfloat162*>(g_rb + (size_t)row * D_DIM);
            #pragma unroll
            for (int i = 0; i < 6; ++i) d[lane + 32 * i] = z;
            if (lane == 0) g_rinv[row] = 0.0f;
            return;
        }
        src = rules + (size_t)row * D_DIM;
        dst = reinterpret_cast<__nv_bfloat162*>(g_rb + (size_t)row * D_DIM);
    } else {
        int qr = row - N_PAD;
        src = emb + (size_t)qr * D_DIM;
        dst = reinterpret_cast<__nv_bfloat162*>(g_qb + (size_t)qr * D_DIM);
    }

    const float2* s2 = reinterpret_cast<const float2*>(src);
    float2 v[6];
    float ss = 0.0f;
    #pragma unroll
    for (int i = 0; i < 6; ++i) {
        v[i] = s2[lane + 32 * i];
        ss += v[i].x * v[i].x + v[i].y * v[i].y;
    }
    #pragma unroll
    for (int o = 16; o; o >>= 1) ss += __shfl_xor_sync(0xffffffffu, ss, o);
    float inv = 1.0f / fmaxf(sqrtf(ss), 1e-12f);
    #pragma unroll
    for (int i = 0; i < 6; ++i)
        dst[lane + 32 * i] = __float22bfloat162_rn(make_float2(v[i].x * inv, v[i].y * inv));
    if (is_rule && lane == 0) g_rinv[row] = inv;
}

// ---------------- fused bf16 sims GEMM + streaming top-8, 148 CTAs ---------
__device__ __forceinline__ void issue_b_chunk(uint32_t sbB, int tid, int ch, int t0) {
    int t  = ch / KCH;
    int kc = ch - t * KCH;
    const __nv_bfloat16* src = g_rb + (size_t)(t0 + t) * (BN * D_DIM) + kc * BK;
    uint32_t bbase = sbB + (uint32_t)(ch % 3) * (BN * BSTRIDE * 2);
    #pragma unroll
    for (int i = 0; i < 2; ++i) {   // 128 rows * 8 uint4 = 1024 / 512 thr
        int e = tid + i * NTHREADS;
        int r = e >> 3;
        int u = e & 7;
        cp16(bbase + (uint32_t)(r * BSTRIDE + u * 8) * 2, src + (size_t)r * D_DIM + u * 8);
    }
    asm volatile("cp.async.commit_group;" ::: "memory");
}

__device__ void topk_insert(SimsSmem* sm, int r, float v, int j) {
    bool done = false;
    while (!done) {
        if (atomicCAS(&sm->lck[r], 0, 1) == 0) {
            volatile float* tv = sm->topv + r * TOPK;
            volatile int*   ti = sm->topi + r * TOPK;
            float mn = tv[0]; int mp = 0;
            #pragma unroll
            for (int p = 1; p < TOPK; ++p) { float x = tv[p]; if (x < mn) { mn = x; mp = p; } }
            if (v > mn) {
                tv[mp] = v;
                ti[mp] = j;
                float nm = v;
                #pragma unroll
                for (int p = 0; p < TOPK; ++p) { float x = tv[p]; if (x < nm) nm = x; }
                sm->thr[r] = nm;
            }
            __threadfence_block();
            atomicExch(&sm->lck[r], 0);
            done = true;
        }
    }
}

__global__ __launch_bounds__(NTHREADS, 1)
void sims_topk_kernel() {
    extern __shared__ char smraw[];
    SimsSmem* sm = reinterpret_cast<SimsSmem*>(smraw);
    const uint32_t sbA = smem_u32(sm->As);
    const uint32_t sbB = smem_u32(sm->Bs);

    const int tid  = threadIdx.x;
    const int lane = tid & 31;
    const int wid  = tid >> 5;            // 0..15
    const int wm   = (wid & 3) * 32;      // 4 m-warps over 128 rows
    const int wn   = (wid >> 2) * 32;     // 4 n-warps over 128 cols
    const int cta  = blockIdx.x;

    const int u0 = ustart(cta);
    const int u1 = ustart(cta + 1);

    // decompose range into <=2 (group, tile-range) sections
    int sg[2], st[2], sn[2], nsec;
    {
        int g0 = u0 / GTILES, g1 = (u1 - 1) / GTILES;
        sg[0] = g0; st[0] = u0 - g0 * GTILES;
        if (g0 == g1) { sn[0] = u1 - u0; nsec = 1; sg[1] = g0; st[1] = 0; sn[1] = 0; }
        else {
            sn[0] = (g0 + 1) * GTILES - u0;
            sg[1] = g1; st[1] = 0; sn[1] = u1 - g1 * GTILES;
            nsec = 2;
        }
    }

    // ldmatrix lane addressing (element units)
    const int a_row = (lane & 15);
    const int a_kof = (lane >> 4) << 3;
    const int b_row = ((lane >> 4) << 3) + (lane & 7);
    const int b_kof = ((lane >> 3) & 1) << 3;

    volatile float* vthr = sm->thr;

    for (int s = 0; s < nsec; ++s) {
        const int g    = sg[s];
        const int t0   = st[s];
        const int nt   = sn[s];
        const int row0 = g * BM;
        const int TOTC = nt * KCH;

        // slot: index of this section within group = cta - (CTA containing unit g*GTILES)
        int cf = (g * GTILES * 37) / 6272;
        while (ustart(cf + 1) <= g * GTILES) ++cf;
        while (ustart(cf) > g * GTILES) --cf;
        const int slot = cta - cf;

        // init top-k state
        for (int i = tid; i < BM * TOPK; i += NTHREADS) { sm->topv[i] = -FLT_MAX; sm->topi[i] = 0; }
        for (int i = tid; i < BM; i += NTHREADS)        { sm->thr[i]  = -FLT_MAX; sm->lck[i]  = 0; }

        // resident A: 128 rows x 384 bf16
        {
            const uint4* gq = reinterpret_cast<const uint4*>(g_qb + (size_t)row0 * D_DIM);
            for (int i = tid; i < BM * 48; i += NTHREADS) {
                int r = i / 48, u = i - (i / 48) * 48;
                *reinterpret_cast<uint4*>(
                    reinterpret_cast<char*>(sm->As) + (size_t)r * (ASTRIDE * 2) + u * 16) =
                    gq[(size_t)r * 48 + u];
            }
        }

        issue_b_chunk(sbB, tid, 0, t0);
        if (TOTC > 1) issue_b_chunk(sbB, tid, 1, t0);

        float c[2][4][4];
        int t = t0, kc = 0;
        for (int ch = 0; ch < TOTC; ++ch) {
            if (kc == 0) {
                #pragma unroll
                for (int mi = 0; mi < 2; ++mi)
                    #pragma unroll
                    for (int nq = 0; nq < 4; ++nq)
                        #pragma unroll
                        for (int e = 0; e < 4; ++e) c[mi][nq][e] = 0.0f;
            }

            if (ch >= TOTC - 2)
                asm volatile("cp.async.wait_group 0;" ::: "memory");
            else
                asm volatile("cp.async.wait_group 1;" ::: "memory");
            __syncthreads();

            if (ch + 2 < TOTC) issue_b_chunk(sbB, tid, ch + 2, t0);

            const uint32_t bB = sbB + (uint32_t)(ch % 3) * (BN * BSTRIDE * 2);
            const int k0 = kc * BK;

            #pragma unroll
            for (int ks = 0; ks < 4; ++ks) {
                const int k = k0 + ks * 16;
                uint32_t a[2][4];
                #pragma unroll
                for (int mi = 0; mi < 2; ++mi)
                    ldsm_x4(a[mi], sbA + (uint32_t)((wm + mi * 16 + a_row) * ASTRIDE + k + a_kof) * 2);
                uint32_t b[2][4];
                #pragma unroll
                for (int nt2 = 0; nt2 < 2; ++nt2)
                    ldsm_x4(b[nt2], bB + (uint32_t)((wn + nt2 * 16 + b_row) * BSTRIDE + ks * 16 + b_kof) * 2);
                #pragma unroll
                for (int mi = 0; mi < 2; ++mi)
                    #pragma unroll
                    for (int nq = 0; nq < 4; ++nq)
                        mma16816(c[mi][nq], a[mi],
                                 b[nq >> 1][(nq & 1) * 2], b[nq >> 1][(nq & 1) * 2 + 1]);
            }

            if (kc == KCH - 1) {
                const int jb = t * BN;
                #pragma unroll
                for (int mi = 0; mi < 2; ++mi) {
                    #pragma unroll
                    for (int h = 0; h < 2; ++h) {
                        const int r = wm + mi * 16 + (lane >> 2) + h * 8;
                        float cthr = vthr[r];   // monotone: stale => only extra inserts
                        #pragma unroll
                        for (int nq = 0; nq < 4; ++nq) {
                            #pragma unroll
                            for (int e = 0; e < 2; ++e) {
                                float v = c[mi][nq][h * 2 + e];
                                int j = jb + wn + nq * 8 + (lane & 3) * 2 + e;
                                if (v > cthr && j < N_RULES) {
                                    topk_insert(sm, r, v, j);
                                    cthr = vthr[r];
                                }
                            }
                        }
                    }
                }
            }

            if (++kc == KCH) { kc = 0; ++t; }
        }
        __syncthreads();

        // write this section's per-row top-8 into its slot
        for (int i = tid; i < BM * TOPK; i += NTHREADS) {
            int r = i >> 3, p = i & 7;
            size_t o = (size_t)(row0 + r) * NCAND + slot * TOPK + p;
            g_topv[o] = sm->topv[i];
            g_topi[o] = sm->topi[i];
        }
        __syncthreads();   // writeout reads done before next section re-inits smem
    }
}

// ---------------- epilogue: merge32 -> softmax -> gather -> gelu -> LN -----
#define ER 16
__global__ __launch_bounds__(256)
void epilogue_kernel(const float* __restrict__ s0,
                     const float* __restrict__ rules_raw,
                     const float* __restrict__ W,
                     const float* __restrict__ bvec,
                     const float* __restrict__ alpha_p,
                     const float* __restrict__ gamma,
                     const float* __restrict__ beta,
                     float* __restrict__ out) {
    __shared__ float ctx[ER][D_DIM];
    __shared__ float xs[ER][H_DIM];
    __shared__ float w8[ER][TOPK];
    __shared__ int   i8[ER][TOPK];
    __shared__ float mu_s[ER], rs_s[ER];

    const int tid = threadIdx.x;  // 256
    const int r0  = blockIdx.x * ER;

    if (tid < ER) {
        int r = r0 + tid;
        float cv[NCAND]; int ci[NCAND];
        #pragma unroll
        for (int q = 0; q < NCAND; ++q) {
            cv[q] = g_topv[(size_t)r * NCAND + q];
            ci[q] = g_topi[(size_t)r * NCAND + q];
        }
        float v[TOPK];
        #pragma unroll
        for (int p = 0; p < TOPK; ++p) {
            float bm = -FLT_MAX; int bq = 0;
            #pragma unroll
            for (int q = 0; q < NCAND; ++q)
                if (cv[q] > bm) { bm = cv[q]; bq = q; }
            v[p] = bm;
            #pragma unroll
            for (int q = 0; q < NCAND; ++q)
                if (q == bq) { i8[tid][p] = ci[q]; cv[q] = -FLT_MAX; }
        }
        float m = v[0];
        float s = 0.0f;
        #pragma unroll
        for (int p = 0; p < TOPK; ++p) { v[p] = expf(v[p] - m); s += v[p]; }
        float inv = 1.0f / s;
        #pragma unroll
        for (int p = 0; p < TOPK; ++p) w8[tid][p] = v[p] * inv;
    }
    __syncthreads();

    // gather rule context
    for (int e = tid; e < ER * D_DIM; e += 256) {
        int r = e / D_DIM, d = e - r * D_DIM;
        float acc = 0.0f;
        #pragma unroll
        for (int k = 0; k < TOPK; ++k) {
            int idx = i8[r][k];
            acc += w8[r][k] * rules_raw[(size_t)idx * D_DIM + d] * g_rinv[idx];
        }
        ctx[r][d] = acc;
    }
    __syncthreads();

    // GEMM: thread handles 2 columns (h0, h1=h0+128) x 8 rows
    const float alpha = *alpha_p;
    const int h0 = tid & 127;
    const int h1 = h0 + 128;
    const int rb = (tid >> 7) * 8;       // 0 or 8

    float acc0[8], acc1[8];
    #pragma unroll
    for (int r = 0; r < 8; ++r) { acc0[r] = 0.0f; acc1[r] = 0.0f; }

    const float4* wr0 = reinterpret_cast<const float4*>(W + (size_t)h0 * D_DIM);
    const float4* wr1 = reinterpret_cast<const float4*>(W + (size_t)h1 * D_DIM);
    #pragma unroll 2
    for (int dq = 0; dq < D_DIM / 4; ++dq) {
        float4 wa = wr0[dq];
        float4 wb = wr1[dq];
        #pragma unroll
        for (int r = 0; r < 8; ++r) {
            float4 c4 = *reinterpret_cast<const float4*>(&ctx[rb + r][dq * 4]);
            acc0[r] += wa.x * c4.x + wa.y * c4.y + wa.z * c4.z + wa.w * c4.w;
            acc1[r] += wb.x * c4.x + wb.y * c4.y + wb.z * c4.z + wb.w * c4.w;
        }
    }
    const float b0 = bvec[h0], b1 = bvec[h1];
    #pragma unroll
    for (int r = 0; r < 8; ++r) {
        float z0 = acc0[r] + b0;
        float g0 = 0.5f * z0 * (1.0f + erff(z0 * 0.70710678118654752f));
        xs[rb + r][h0] = s0[(size_t)(r0 + rb + r) * H_DIM + h0] + alpha * g0;
        float z1 = acc1[r] + b1;
        float g1 = 0.5f * z1 * (1.0f + erff(z1 * 0.70710678118654752f));
        xs[rb + r][h1] = s0[(size_t)(r0 + rb + r) * H_DIM + h1] + alpha * g1;
    }
    __syncthreads();

    // LN stats: warp w handles rows w, w+8
    const int w = tid >> 5, lane = tid & 31;
    for (int rr = w; rr < ER; rr += 8) {
        float s = 0.0f, s2 = 0.0f;
        #pragma unroll
        for (int q = 0; q < 8; ++q) {
            float x = xs[rr][lane + 32 * q];
            s += x; s2 += x * x;
        }
        for (int o = 16; o; o >>= 1) {
            s  += __shfl_xor_sync(0xffffffffu, s, o);
            s2 += __shfl_xor_sync(0xffffffffu, s2, o);
        }
        if (lane == 0) {
            float mu  = s * (1.0f / 256.0f);
            float var = s2 * (1.0f / 256.0f) - mu * mu;
            mu_s[rr] = mu;
            rs_s[rr] = rsqrtf(var + 1e-5f);
        }
    }
    __syncthreads();

    const float gm0 = gamma[h0], bt0 = beta[h0];
    const float gm1 = gamma[h1], bt1 = beta[h1];
    #pragma unroll
    for (int r = 0; r < 8; ++r) {
        float mu = mu_s[rb + r], rs = rs_s[rb + r];
        out[(size_t)(r0 + rb + r) * H_DIM + h0] = (xs[rb + r][h0] - mu) * rs * gm0 + bt0;
        out[(size_t)(r0 + rb + r) * H_DIM + h1] = (xs[rb + r][h1] - mu) * rs * gm1 + bt1;
    }
}

// ---------------- launch ----------------------------------------------------
extern "C" void kernel_launch(void* const* d_in, const int* in_sizes, int n_in,
                              void* d_out, int out_size) {
    const float* embeddings = (const float*)d_in[0];
    const float* s0         = (const float*)d_in[1];
    const float* rules      = (const float*)d_in[2];
    const float* W          = (const float*)d_in[3];
    const float* b          = (const float*)d_in[4];
    const float* alpha      = (const float*)d_in[5];
    const float* gamma      = (const float*)d_in[6];
    const float* beta       = (const float*)d_in[7];
    float* out = (float*)d_out;
    (void)in_sizes; (void)n_in; (void)out_size;

    cudaFuncSetAttribute(sims_topk_kernel,
                         cudaFuncAttributeMaxDynamicSharedMemorySize,
                         (int)sizeof(SimsSmem));

    prep_all_kernel<<<(N_PAD + B_ROWS) / 8, 256>>>(rules, embeddings);
    init_cand_kernel<<<(B_ROWS * NCAND) / 256, 256>>>();
    sims_topk_kernel<<<NCTAS, NTHREADS, sizeof(SimsSmem)>>>();
    epilogue_kernel<<<B_ROWS / ER, 256>>>(s0, rules, W, b, alpha, gamma, beta, out);
}

// round 14
// speedup vs baseline: 1.0853x; 1.0853x over previous
#include <cuda_runtime.h>
#include <cuda_bf16.h>
#include <math.h>
#include <stdint.h>
#include <float.h>

#define N_RULES 50000
#define N_PAD   50176            // 392 * 128
#define NHALF   25088            // rules per CTA-half
#define TILES   196              // NHALF / 128
#define D_DIM   384
#define B_ROWS  8192
#define H_DIM   256
#define TOPK    8
#define NCAND   16               // 2 halves * 8

#define BM 128
#define BN 128
#define BK 64
#define KCH 6                    // 384 / 64
#define TOT (TILES * KCH)        // 1176
#define ASTRIDE 392              // elems: 384 + 8 (784B row, LDSM conflict-free)
#define BSTRIDE 72               // elems: 64 + 8  (144B row)
#define NTHREADS 512

// ---------------- device scratch ----------------
__device__ __nv_bfloat16 g_rules[(size_t)N_PAD * D_DIM];
__device__ float         g_rinv[N_PAD];
__device__ __nv_bfloat16 g_q[(size_t)B_ROWS * D_DIM];
__device__ float         g_topv[(size_t)B_ROWS * NCAND];
__device__ int           g_topi[(size_t)B_ROWS * NCAND];

// ---------------- smem struct ----------------
struct __align__(16) SimsSmem {
    __nv_bfloat16 As[BM * ASTRIDE];     // 100352 B
    __nv_bfloat16 Bs[3][BN * BSTRIDE];  // 55296 B
    float topv[BM * TOPK];
    int   topi[BM * TOPK];
    float thr[BM];
    int   lck[BM];
};

// ---------------- PTX helpers ----------------
__device__ __forceinline__ uint32_t smem_u32(const void* p) {
    uint32_t a;
    asm("{ .reg .u64 t; cvta.to.shared.u64 t, %1; cvt.u32.u64 %0, t; }" : "=r"(a) : "l"(p));
    return a;
}
__device__ __forceinline__ void cp16(uint32_t dst, const void* src) {
    asm volatile("cp.async.cg.shared.global [%0], [%1], 16;" :: "r"(dst), "l"(src));
}
__device__ __forceinline__ void ldsm_x4(uint32_t* r, uint32_t addr) {
    asm volatile("ldmatrix.sync.aligned.m8n8.x4.shared.b16 {%0,%1,%2,%3}, [%4];"
                 : "=r"(r[0]), "=r"(r[1]), "=r"(r[2]), "=r"(r[3]) : "r"(addr));
}
__device__ __forceinline__ void mma16816(float* c, const uint32_t* a,
                                         uint32_t b0, uint32_t b1) {
    asm volatile(
        "mma.sync.aligned.m16n8k16.row.col.f32.bf16.bf16.f32 "
        "{%0,%1,%2,%3}, {%4,%5,%6,%7}, {%8,%9}, {%0,%1,%2,%3};\n"
        : "+f"(c[0]), "+f"(c[1]), "+f"(c[2]), "+f"(c[3])
        : "r"(a[0]), "r"(a[1]), "r"(a[2]), "r"(a[3]), "r"(b0), "r"(b1));
}

// ---------------- fused prep: warp-per-row normalize + bf16 cast ------------
// rows [0, N_PAD): rules (pad rows -> zeros); rows [N_PAD, N_PAD+B_ROWS): q
__global__ __launch_bounds__(256)
void prep_all_kernel(const float* __restrict__ rules, const float* __restrict__ emb) {
    const int warp = threadIdx.x >> 5;
    const int lane = threadIdx.x & 31;
    const int row  = blockIdx.x * 8 + warp;

    const float* src;
    __nv_bfloat162* dst;
    bool is_rule = (row < N_PAD);
    if (is_rule) {
        if (row >= N_RULES) {   // pad rows: zero
            __nv_bfloat162 z = __float22bfloat162_rn(make_float2(0.f, 0.f));
            __nv_bfloat162* d = reinterpret_cast<__nv_bfloat162*>(g_rules + (size_t)row * D_DIM);
            #pragma unroll
            for (int i = 0; i < 6; ++i) d[lane + 32 * i] = z;
            if (lane == 0) g_rinv[row] = 0.0f;
            return;
        }
        src = rules + (size_t)row * D_DIM;
        dst = reinterpret_cast<__nv_bfloat162*>(g_rules + (size_t)row * D_DIM);
    } else {
        int qr = row - N_PAD;
        src = emb + (size_t)qr * D_DIM;
        dst = reinterpret_cast<__nv_bfloat162*>(g_q + (size_t)qr * D_DIM);
    }

    const float2* s2 = reinterpret_cast<const float2*>(src);
    float2 v[6];
    float ss = 0.0f;
    #pragma unroll
    for (int i = 0; i < 6; ++i) {
        v[i] = s2[lane + 32 * i];
        ss += v[i].x * v[i].x + v[i].y * v[i].y;
    }
    #pragma unroll
    for (int o = 16; o; o >>= 1) ss += __shfl_xor_sync(0xffffffffu, ss, o);
    float inv = 1.0f / fmaxf(sqrtf(ss), 1e-12f);
    #pragma unroll
    for (int i = 0; i < 6; ++i)
        dst[lane + 32 * i] = __float22bfloat162_rn(make_float2(v[i].x * inv, v[i].y * inv));
    if (is_rule && lane == 0) g_rinv[row] = inv;
}

// ---------------- fused bf16 sims GEMM + streaming top-8 -------------------
__device__ __forceinline__ void issue_b_chunk(uint32_t sbB, int tid, int ch, int rule0) {
    int t  = ch / KCH;
    int kc = ch - t * KCH;
    const __nv_bfloat16* src = g_rules + ((size_t)rule0 + (size_t)t * BN) * D_DIM + kc * BK;
    uint32_t bbase = sbB + (uint32_t)(ch % 3) * (BN * BSTRIDE * 2);
    #pragma unroll
    for (int i = 0; i < 2; ++i) {   // 128 rows * 8 uint4 = 1024 / 512 thr
        int e = tid + i * NTHREADS;
        int r = e >> 3;
        int u = e & 7;
        cp16(bbase + (uint32_t)(r * BSTRIDE + u * 8) * 2, src + (size_t)r * D_DIM + u * 8);
    }
    asm volatile("cp.async.commit_group;" ::: "memory");
}

__device__ void topk_insert(SimsSmem* sm, int r, float v, int j) {
    bool done = false;
    while (!done) {
        if (atomicCAS(&sm->lck[r], 0, 1) == 0) {
            volatile float* tv = sm->topv + r * TOPK;
            volatile int*   ti = sm->topi + r * TOPK;
            float mn = tv[0]; int mp = 0;
            #pragma unroll
            for (int p = 1; p < TOPK; ++p) { float x = tv[p]; if (x < mn) { mn = x; mp = p; } }
            if (v > mn) {
                tv[mp] = v;
                ti[mp] = j;
                float nm = v;
                #pragma unroll
                for (int p = 0; p < TOPK; ++p) { float x = tv[p]; if (x < nm) nm = x; }
                sm->thr[r] = nm;
            }
            __threadfence_block();
            atomicExch(&sm->lck[r], 0);
            done = true;
        }
    }
}

__global__ __launch_bounds__(NTHREADS, 1)
void sims_topk_kernel() {
    extern __shared__ char smraw[];
    SimsSmem* sm = reinterpret_cast<SimsSmem*>(smraw);
    const uint32_t sbA = smem_u32(sm->As);
    const uint32_t sbB = smem_u32(sm->Bs);

    const int tid    = threadIdx.x;
    const int lane   = tid & 31;
    const int wid    = tid >> 5;            // 0..15
    const int wm     = (wid & 3) * 32;      // 4 m-warps over 128 rows
    const int wn     = (wid >> 2) * 32;     // 4 n-warps over 128 cols
    const int grp    = blockIdx.x >> 1;
    const int half   = blockIdx.x & 1;
    const int row0   = grp * BM;
    const int rule0  = half * NHALF;

    // init top-k state
    for (int i = tid; i < BM * TOPK; i += NTHREADS) { sm->topv[i] = -FLT_MAX; sm->topi[i] = 0; }
    for (int i = tid; i < BM; i += NTHREADS)        { sm->thr[i]  = -FLT_MAX; sm->lck[i]  = 0; }

    // resident A: 128 rows x 384 bf16
    {
        const uint4* gq = reinterpret_cast<const uint4*>(g_q + (size_t)row0 * D_DIM);
        for (int i = tid; i < BM * 48; i += NTHREADS) {
            int r = i / 48, u = i - (i / 48) * 48;
            *reinterpret_cast<uint4*>(
                reinterpret_cast<char*>(sm->As) + (size_t)r * (ASTRIDE * 2) + u * 16) =
                gq[(size_t)r * 48 + u];
        }
    }

    issue_b_chunk(sbB, tid, 0, rule0);
    issue_b_chunk(sbB, tid, 1, rule0);

    // ldmatrix lane addressing (element units)
    const int a_row = (lane & 15);
    const int a_kof = (lane >> 4) << 3;
    const int b_row = ((lane >> 4) << 3) + (lane & 7);
    const int b_kof = ((lane >> 3) & 1) << 3;

    volatile float* vthr = sm->thr;
    float c[2][4][4];

    int t = 0, kc = 0;
    for (int ch = 0; ch < TOT; ++ch) {
        if (kc == 0) {
            #pragma unroll
            for (int mi = 0; mi < 2; ++mi)
                #pragma unroll
                for (int nq = 0; nq < 4; ++nq)
                    #pragma unroll
                    for (int e = 0; e < 4; ++e) c[mi][nq][e] = 0.0f;
        }

        if (ch == TOT - 1)
            asm volatile("cp.async.wait_group 0;" ::: "memory");
        else
            asm volatile("cp.async.wait_group 1;" ::: "memory");
        __syncthreads();

        if (ch + 2 < TOT) issue_b_chunk(sbB, tid, ch + 2, rule0);

        const uint32_t bB = sbB + (uint32_t)(ch % 3) * (BN * BSTRIDE * 2);
        const int k0 = kc * BK;

        #pragma unroll
        for (int ks = 0; ks < 4; ++ks) {
            const int k = k0 + ks * 16;
            uint32_t a[2][4];
            #pragma unroll
            for (int mi = 0; mi < 2; ++mi)
                ldsm_x4(a[mi], sbA + (uint32_t)((wm + mi * 16 + a_row) * ASTRIDE + k + a_kof) * 2);
            uint32_t b[2][4];
            #pragma unroll
            for (int nt = 0; nt < 2; ++nt)
                ldsm_x4(b[nt], bB + (uint32_t)((wn + nt * 16 + b_row) * BSTRIDE + ks * 16 + b_kof) * 2);
            #pragma unroll
            for (int mi = 0; mi < 2; ++mi)
                #pragma unroll
                for (int nq = 0; nq < 4; ++nq)
                    mma16816(c[mi][nq], a[mi],
                             b[nq >> 1][(nq & 1) * 2], b[nq >> 1][(nq & 1) * 2 + 1]);
        }

        if (kc == KCH - 1) {
            const int jb = rule0 + t * BN;
            #pragma unroll
            for (int mi = 0; mi < 2; ++mi) {
                #pragma unroll
                for (int h = 0; h < 2; ++h) {
                    const int r = wm + mi * 16 + (lane >> 2) + h * 8;
                    float cthr = vthr[r];   // monotone: stale => only extra inserts
                    #pragma unroll
                    for (int nq = 0; nq < 4; ++nq) {
                        #pragma unroll
                        for (int e = 0; e < 2; ++e) {
                            float v = c[mi][nq][h * 2 + e];
                            int j = jb + wn + nq * 8 + (lane & 3) * 2 + e;
                            if (v > cthr && j < N_RULES) {
                                topk_insert(sm, r, v, j);
                                cthr = vthr[r];
                            }
                        }
                    }
                }
            }
        }

        if (++kc == KCH) { kc = 0; ++t; }
    }
    __syncthreads();

    // write per-row candidates (this half's top-8)
    for (int i = tid; i < BM * TOPK; i += NTHREADS) {
        int r = i >> 3, p = i & 7;
        g_topv[(size_t)(row0 + r) * NCAND + half * TOPK + p] = sm->topv[i];
        g_topi[(size_t)(row0 + r) * NCAND + half * TOPK + p] = sm->topi[i];
    }
}

// ---------------- epilogue: merge16 -> softmax -> gather -> gelu -> LN -----
#define ER 16
__global__ __launch_bounds__(256)
void epilogue_kernel(const float* __restrict__ s0,
                     const float* __restrict__ rules_raw,
                     const float* __restrict__ W,
                     const float* __restrict__ bvec,
                     const float* __restrict__ alpha_p,
                     const float* __restrict__ gamma,
                     const float* __restrict__ beta,
                     float* __restrict__ out) {
    __shared__ float ctx[ER][D_DIM];
    __shared__ float xs[ER][H_DIM];
    __shared__ float w8[ER][TOPK];
    __shared__ int   i8[ER][TOPK];
    __shared__ float mu_s[ER], rs_s[ER];

    const int tid = threadIdx.x;  // 256
    const int r0  = blockIdx.x * ER;

    if (tid < ER) {
        int r = r0 + tid;
        float cv[NCAND]; int ci[NCAND];
        #pragma unroll
        for (int q = 0; q < NCAND; ++q) {
            cv[q] = g_topv[(size_t)r * NCAND + q];
            ci[q] = g_topi[(size_t)r * NCAND + q];
        }
        float v[TOPK];
        #pragma unroll
        for (int p = 0; p < TOPK; ++p) {
            float bm = -FLT_MAX; int bq = 0;
            #pragma unroll
            for (int q = 0; q < NCAND; ++q)
                if (cv[q] > bm) { bm = cv[q]; bq = q; }
            v[p] = bm;
            #pragma unroll
            for (int q = 0; q < NCAND; ++q)
                if (q == bq) { i8[tid][p] = ci[q]; cv[q] = -FLT_MAX; }
        }
        float m = v[0];
        float s = 0.0f;
        #pragma unroll
        for (int p = 0; p < TOPK; ++p) { v[p] = expf(v[p] - m); s += v[p]; }
        float inv = 1.0f / s;
        #pragma unroll
        for (int p = 0; p < TOPK; ++p) w8[tid][p] = v[p] * inv;
    }
    __syncthreads();

    for (int e = tid; e < ER * D_DIM; e += 256) {
        int r = e / D_DIM, d = e - r * D_DIM;
        float acc = 0.0f;
        #pragma unroll
        for (int k = 0; k < TOPK; ++k) {
            int idx = i8[r][k];
            acc += w8[r][k] * rules_raw[(size_t)idx * D_DIM + d] * g_rinv[idx];
        }
        ctx[r][d] = acc;
    }
    __syncthreads();

    const float alpha = *alpha_p;
    const int h = tid;
    float acc[ER];
    #pragma unroll
    for (int r = 0; r < ER; ++r) acc[r] = 0.0f;

    const float4* wr = reinterpret_cast<const float4*>(W + (size_t)h * D_DIM);
    #pragma unroll 4
    for (int dq = 0; dq < D_DIM / 4; ++dq) {
        float4 w4 = wr[dq];
        #pragma unroll
        for (int r = 0; r < ER; ++r) {
            float4 c4 = *reinterpret_cast<const float4*>(&ctx[r][dq * 4]);
            acc[r] += w4.x * c4.x + w4.y * c4.y + w4.z * c4.z + w4.w * c4.w;
        }
    }
    const float bb = bvec[h];
    #pragma unroll
    for (int r = 0; r < ER; ++r) {
        float z = acc[r] + bb;
        float g = 0.5f * z * (1.0f + erff(z * 0.70710678118654752f));
        xs[r][h] = s0[(size_t)(r0 + r) * H_DIM + h] + alpha * g;
    }
    __syncthreads();

    const int w = tid >> 5, lane = tid & 31;
    for (int rr = w; rr < ER; rr += 8) {
        float s = 0.0f, s2 = 0.0f;
        #pragma unroll
        for (int q = 0; q < 8; ++q) {
            float x = xs[rr][lane + 32 * q];
            s += x; s2 += x * x;
        }
        for (int o = 16; o; o >>= 1) {
            s  += __shfl_xor_sync(0xffffffffu, s, o);
            s2 += __shfl_xor_sync(0xffffffffu, s2, o);
        }
        if (lane == 0) {
            float mu  = s * (1.0f / 256.0f);
            float var = s2 * (1.0f / 256.0f) - mu * mu;
            mu_s[rr] = mu;
            rs_s[rr] = rsqrtf(var + 1e-5f);
        }
    }
    __syncthreads();

    const float gm = gamma[h], bt = beta[h];
    #pragma unroll
    for (int r = 0; r < ER; ++r)
        out[(size_t)(r0 + r) * H_DIM + h] = (xs[r][h] - mu_s[r]) * rs_s[r] * gm + bt;
}

// ---------------- launch ----------------------------------------------------
extern "C" void kernel_launch(void* const* d_in, const int* in_sizes, int n_in,
                              void* d_out, int out_size) {
    const float* embeddings = (const float*)d_in[0];
    const float* s0         = (const float*)d_in[1];
    const float* rules      = (const float*)d_in[2];
    const float* W          = (const float*)d_in[3];
    const float* b          = (const float*)d_in[4];
    const float* alpha      = (const float*)d_in[5];
    const float* gamma      = (const float*)d_in[6];
    const float* beta       = (const float*)d_in[7];
    float* out = (float*)d_out;
    (void)in_sizes; (void)n_in; (void)out_size;

    cudaFuncSetAttribute(sims_topk_kernel,
                         cudaFuncAttributeMaxDynamicSharedMemorySize,
                         (int)sizeof(SimsSmem));

    prep_all_kernel<<<(N_PAD + B_ROWS) / 8, 256>>>(rules, embeddings);
    sims_topk_kernel<<<128, NTHREADS, sizeof(SimsSmem)>>>();
    epilogue_kernel<<<B_ROWS / ER, 256>>>(s0, rules, W, b, alpha, gamma, beta, out);
}

// round 15
// speedup vs baseline: 1.1150x; 1.0274x over previous
#include <cuda_runtime.h>
#include <cuda_bf16.h>
#include <math.h>
#include <stdint.h>
#include <float.h>

#define N_RULES 50000
#define N_PAD   50176            // 392 * 128
#define NHALF   25088            // rules per CTA-half
#define TILES   196              // NHALF / 128
#define D_DIM   384
#define B_ROWS  8192
#define H_DIM   256
#define TOPK    8
#define NCAND   16               // 2 halves * 8

#define BM 64
#define BN 128
#define BK 64
#define KCH 6                    // 384 / 64
#define TOT (TILES * KCH)        // 1176
#define ASTRIDE 392              // elems: 384 + 8 (784B row, LDSM conflict-free)
#define BSTRIDE 72               // elems: 64 + 8  (144B row)
#define NTHREADS 256

// ---------------- device scratch ----------------
__device__ __nv_bfloat16 g_rules[(size_t)N_PAD * D_DIM];
__device__ float         g_rinv[N_PAD];
__device__ __nv_bfloat16 g_q[(size_t)B_ROWS * D_DIM];
__device__ float         g_topv[(size_t)B_ROWS * NCAND];
__device__ int           g_topi[(size_t)B_ROWS * NCAND];

// ---------------- smem struct ----------------
struct __align__(16) SimsSmem {
    __nv_bfloat16 As[BM * ASTRIDE];     // 50176 B
    __nv_bfloat16 Bs[3][BN * BSTRIDE];  // 55296 B
    float topv[BM * TOPK];              // 2048 B
    int   topi[BM * TOPK];              // 2048 B
    float thr[BM];                      // 256 B
    int   lck[BM];                      // 256 B
};                                      // 110080 B -> 2 CTAs / SM

// ---------------- PTX helpers ----------------
__device__ __forceinline__ uint32_t smem_u32(const void* p) {
    uint32_t a;
    asm("{ .reg .u64 t; cvta.to.shared.u64 t, %1; cvt.u32.u64 %0, t; }" : "=r"(a) : "l"(p));
    return a;
}
__device__ __forceinline__ void cp16(uint32_t dst, const void* src) {
    asm volatile("cp.async.cg.shared.global [%0], [%1], 16;" :: "r"(dst), "l"(src));
}
__device__ __forceinline__ void ldsm_x4(uint32_t* r, uint32_t addr) {
    asm volatile("ldmatrix.sync.aligned.m8n8.x4.shared.b16 {%0,%1,%2,%3}, [%4];"
                 : "=r"(r[0]), "=r"(r[1]), "=r"(r[2]), "=r"(r[3]) : "r"(addr));
}
__device__ __forceinline__ void mma16816(float* c, const uint32_t* a,
                                         uint32_t b0, uint32_t b1) {
    asm volatile(
        "mma.sync.aligned.m16n8k16.row.col.f32.bf16.bf16.f32 "
        "{%0,%1,%2,%3}, {%4,%5,%6,%7}, {%8,%9}, {%0,%1,%2,%3};\n"
        : "+f"(c[0]), "+f"(c[1]), "+f"(c[2]), "+f"(c[3])
        : "r"(a[0]), "r"(a[1]), "r"(a[2]), "r"(a[3]), "r"(b0), "r"(b1));
}

// ---------------- fused prep: warp-per-row normalize + bf16 cast ------------
// rows [0, N_PAD): rules (pad rows -> zeros); rows [N_PAD, N_PAD+B_ROWS): q
__global__ __launch_bounds__(256)
void prep_all_kernel(const float* __restrict__ rules, const float* __restrict__ emb) {
    const int warp = threadIdx.x >> 5;
    const int lane = threadIdx.x & 31;
    const int row  = blockIdx.x * 8 + warp;

    const float* src;
    __nv_bfloat162* dst;
    bool is_rule = (row < N_PAD);
    if (is_rule) {
        if (row >= N_RULES) {   // pad rows: zero
            __nv_bfloat162 z = __float22bfloat162_rn(make_float2(0.f, 0.f));
            __nv_bfloat162* d = reinterpret_cast<__nv_bfloat162*>(g_rules + (size_t)row * D_DIM);
            #pragma unroll
            for (int i = 0; i < 6; ++i) d[lane + 32 * i] = z;
            if (lane == 0) g_rinv[row] = 0.0f;
            return;
        }
        src = rules + (size_t)row * D_DIM;
        dst = reinterpret_cast<__nv_bfloat162*>(g_rules + (size_t)row * D_DIM);
    } else {
        int qr = row - N_PAD;
        src = emb + (size_t)qr * D_DIM;
        dst = reinterpret_cast<__nv_bfloat162*>(g_q + (size_t)qr * D_DIM);
    }

    const float2* s2 = reinterpret_cast<const float2*>(src);
    float2 v[6];
    float ss = 0.0f;
    #pragma unroll
    for (int i = 0; i < 6; ++i) {
        v[i] = s2[lane + 32 * i];
        ss += v[i].x * v[i].x + v[i].y * v[i].y;
    }
    #pragma unroll
    for (int o = 16; o; o >>= 1) ss += __shfl_xor_sync(0xffffffffu, ss, o);
    float inv = 1.0f / fmaxf(sqrtf(ss), 1e-12f);
    #pragma unroll
    for (int i = 0; i < 6; ++i)
        dst[lane + 32 * i] = __float22bfloat162_rn(make_float2(v[i].x * inv, v[i].y * inv));
    if (is_rule && lane == 0) g_rinv[row] = inv;
}

// ---------------- fused bf16 sims GEMM + streaming top-8 (occ 2) -----------
__device__ __forceinline__ void issue_b_chunk(uint32_t sbB, int tid, int ch, int rule0) {
    int t  = ch / KCH;
    int kc = ch - t * KCH;
    const __nv_bfloat16* src = g_rules + ((size_t)rule0 + (size_t)t * BN) * D_DIM + kc * BK;
    uint32_t bbase = sbB + (uint32_t)(ch % 3) * (BN * BSTRIDE * 2);
    #pragma unroll
    for (int i = 0; i < 4; ++i) {   // 128 rows * 8 uint4 = 1024 / 256 thr
        int e = tid + i * NTHREADS;
        int r = e >> 3;
        int u = e & 7;
        cp16(bbase + (uint32_t)(r * BSTRIDE + u * 8) * 2, src + (size_t)r * D_DIM + u * 8);
    }
    asm volatile("cp.async.commit_group;" ::: "memory");
}

__device__ void topk_insert(SimsSmem* sm, int r, float v, int j) {
    bool done = false;
    while (!done) {
        if (atomicCAS(&sm->lck[r], 0, 1) == 0) {
            volatile float* tv = sm->topv + r * TOPK;
            volatile int*   ti = sm->topi + r * TOPK;
            float mn = tv[0]; int mp = 0;
            #pragma unroll
            for (int p = 1; p < TOPK; ++p) { float x = tv[p]; if (x < mn) { mn = x; mp = p; } }
            if (v > mn) {
                tv[mp] = v;
                ti[mp] = j;
                float nm = v;
                #pragma unroll
                for (int p = 0; p < TOPK; ++p) { float x = tv[p]; if (x < nm) nm = x; }
                sm->thr[r] = nm;
            }
            __threadfence_block();
            atomicExch(&sm->lck[r], 0);
            done = true;
        }
    }
}

__global__ __launch_bounds__(NTHREADS, 2)
void sims_topk_kernel() {
    extern __shared__ char smraw[];
    SimsSmem* sm = reinterpret_cast<SimsSmem*>(smraw);
    const uint32_t sbA = smem_u32(sm->As);
    const uint32_t sbB = smem_u32(sm->Bs);

    const int tid    = threadIdx.x;
    const int lane   = tid & 31;
    const int wid    = tid >> 5;            // 0..7
    const int wm     = (wid & 1) * 32;      // 2 m-warps over 64 rows
    const int wn     = (wid >> 1) * 32;     // 4 n-warps over 128 cols
    const int grp    = blockIdx.x >> 1;
    const int half   = blockIdx.x & 1;
    const int row0   = grp * BM;
    const int rule0  = half * NHALF;

    // init top-k state
    for (int i = tid; i < BM * TOPK; i += NTHREADS) { sm->topv[i] = -FLT_MAX; sm->topi[i] = 0; }
    for (int i = tid; i < BM; i += NTHREADS)        { sm->thr[i]  = -FLT_MAX; sm->lck[i]  = 0; }

    // resident A: 64 rows x 384 bf16
    {
        const uint4* gq = reinterpret_cast<const uint4*>(g_q + (size_t)row0 * D_DIM);
        for (int i = tid; i < BM * 48; i += NTHREADS) {
            int r = i / 48, u = i - (i / 48) * 48;
            *reinterpret_cast<uint4*>(
                reinterpret_cast<char*>(sm->As) + (size_t)r * (ASTRIDE * 2) + u * 16) =
                gq[(size_t)r * 48 + u];
        }
    }

    issue_b_chunk(sbB, tid, 0, rule0);
    issue_b_chunk(sbB, tid, 1, rule0);

    // ldmatrix lane addressing (element units)
    const int a_row = (lane & 15);
    const int a_kof = (lane >> 4) << 3;
    const int b_row = ((lane >> 4) << 3) + (lane & 7);
    const int b_kof = ((lane >> 3) & 1) << 3;

    volatile float* vthr = sm->thr;
    float c[2][4][4];

    int t = 0, kc = 0;
    for (int ch = 0; ch < TOT; ++ch) {
        if (kc == 0) {
            #pragma unroll
            for (int mi = 0; mi < 2; ++mi)
                #pragma unroll
                for (int nq = 0; nq < 4; ++nq)
                    #pragma unroll
                    for (int e = 0; e < 4; ++e) c[mi][nq][e] = 0.0f;
        }

        if (ch == TOT - 1)
            asm volatile("cp.async.wait_group 0;" ::: "memory");
        else
            asm volatile("cp.async.wait_group 1;" ::: "memory");
        __syncthreads();

        if (ch + 2 < TOT) issue_b_chunk(sbB, tid, ch + 2, rule0);

        const uint32_t bB = sbB + (uint32_t)(ch % 3) * (BN * BSTRIDE * 2);
        const int k0 = kc * BK;

        #pragma unroll
        for (int ks = 0; ks < 4; ++ks) {
            const int k = k0 + ks * 16;
            uint32_t a[2][4];
            #pragma unroll
            for (int mi = 0; mi < 2; ++mi)
                ldsm_x4(a[mi], sbA + (uint32_t)((wm + mi * 16 + a_row) * ASTRIDE + k + a_kof) * 2);
            uint32_t b[2][4];
            #pragma unroll
            for (int nt = 0; nt < 2; ++nt)
                ldsm_x4(b[nt], bB + (uint32_t)((wn + nt * 16 + b_row) * BSTRIDE + ks * 16 + b_kof) * 2);
            #pragma unroll
            for (int mi = 0; mi < 2; ++mi)
                #pragma unroll
                for (int nq = 0; nq < 4; ++nq)
                    mma16816(c[mi][nq], a[mi],
                             b[nq >> 1][(nq & 1) * 2], b[nq >> 1][(nq & 1) * 2 + 1]);
        }

        if (kc == KCH - 1) {
            const int jb = rule0 + t * BN;
            #pragma unroll
            for (int mi = 0; mi < 2; ++mi) {
                #pragma unroll
                for (int h = 0; h < 2; ++h) {
                    const int r = wm + mi * 16 + (lane >> 2) + h * 8;
                    float cthr = vthr[r];   // monotone: stale => only extra inserts
                    #pragma unroll
                    for (int nq = 0; nq < 4; ++nq) {
                        #pragma unroll
                        for (int e = 0; e < 2; ++e) {
                            float v = c[mi][nq][h * 2 + e];
                            int j = jb + wn + nq * 8 + (lane & 3) * 2 + e;
                            if (v > cthr && j < N_RULES) {
                                topk_insert(sm, r, v, j);
                                cthr = vthr[r];
                            }
                        }
                    }
                }
            }
        }

        if (++kc == KCH) { kc = 0; ++t; }
    }
    __syncthreads();

    // write per-row candidates (this half's top-8)
    for (int i = tid; i < BM * TOPK; i += NTHREADS) {
        int r = i >> 3, p = i & 7;
        g_topv[(size_t)(row0 + r) * NCAND + half * TOPK + p] = sm->topv[i];
        g_topi[(size_t)(row0 + r) * NCAND + half * TOPK + p] = sm->topi[i];
    }
}

// ---------------- epilogue: merge16 -> softmax -> gather -> gelu -> LN -----
#define ER 16
__global__ __launch_bounds__(256)
void epilogue_kernel(const float* __restrict__ s0,
                     const float* __restrict__ rules_raw,
                     const float* __restrict__ W,
                     const float* __restrict__ bvec,
                     const float* __restrict__ alpha_p,
                     const float* __restrict__ gamma,
                     const float* __restrict__ beta,
                     float* __restrict__ out) {
    __shared__ float ctx[ER][D_DIM];
    __shared__ float xs[ER][H_DIM];
    __shared__ float w8[ER][TOPK];
    __shared__ int   i8[ER][TOPK];
    __shared__ float mu_s[ER], rs_s[ER];

    const int tid = threadIdx.x;  // 256
    const int r0  = blockIdx.x * ER;

    if (tid < ER) {
        int r = r0 + tid;
        float cv[NCAND]; int ci[NCAND];
        #pragma unroll
        for (int q = 0; q < NCAND; ++q) {
            cv[q] = g_topv[(size_t)r * NCAND + q];
            ci[q] = g_topi[(size_t)r * NCAND + q];
        }
        float v[TOPK];
        #pragma unroll
        for (int p = 0; p < TOPK; ++p) {
            float bm = -FLT_MAX; int bq = 0;
            #pragma unroll
            for (int q = 0; q < NCAND; ++q)
                if (cv[q] > bm) { bm = cv[q]; bq = q; }
            v[p] = bm;
            #pragma unroll
            for (int q = 0; q < NCAND; ++q)
                if (q == bq) { i8[tid][p] = ci[q]; cv[q] = -FLT_MAX; }
        }
        float m = v[0];
        float s = 0.0f;
        #pragma unroll
        for (int p = 0; p < TOPK; ++p) { v[p] = expf(v[p] - m); s += v[p]; }
        float inv = 1.0f / s;
        #pragma unroll
        for (int p = 0; p < TOPK; ++p) w8[tid][p] = v[p] * inv;
    }
    __syncthreads();

    for (int e = tid; e < ER * D_DIM; e += 256) {
        int r = e / D_DIM, d = e - r * D_DIM;
        float acc = 0.0f;
        #pragma unroll
        for (int k = 0; k < TOPK; ++k) {
            int idx = i8[r][k];
            acc += w8[r][k] * rules_raw[(size_t)idx * D_DIM + d] * g_rinv[idx];
        }
        ctx[r][d] = acc;
    }
    __syncthreads();

    const float alpha = *alpha_p;
    const int h = tid;
    float acc[ER];
    #pragma unroll
    for (int r = 0; r < ER; ++r) acc[r] = 0.0f;

    const float4* wr = reinterpret_cast<const float4*>(W + (size_t)h * D_DIM);
    #pragma unroll 4
    for (int dq = 0; dq < D_DIM / 4; ++dq) {
        float4 w4 = wr[dq];
        #pragma unroll
        for (int r = 0; r < ER; ++r) {
            float4 c4 = *reinterpret_cast<const float4*>(&ctx[r][dq * 4]);
            acc[r] += w4.x * c4.x + w4.y * c4.y + w4.z * c4.z + w4.w * c4.w;
        }
    }
    const float bb = bvec[h];
    #pragma unroll
    for (int r = 0; r < ER; ++r) {
        float z = acc[r] + bb;
        float g = 0.5f * z * (1.0f + erff(z * 0.70710678118654752f));
        xs[r][h] = s0[(size_t)(r0 + r) * H_DIM + h] + alpha * g;
    }
    __syncthreads();

    const int w = tid >> 5, lane = tid & 31;
    for (int rr = w; rr < ER; rr += 8) {
        float s = 0.0f, s2 = 0.0f;
        #pragma unroll
        for (int q = 0; q < 8; ++q) {
            float x = xs[rr][lane + 32 * q];
            s += x; s2 += x * x;
        }
        for (int o = 16; o; o >>= 1) {
            s  += __shfl_xor_sync(0xffffffffu, s, o);
            s2 += __shfl_xor_sync(0xffffffffu, s2, o);
        }
        if (lane == 0) {
            float mu  = s * (1.0f / 256.0f);
            float var = s2 * (1.0f / 256.0f) - mu * mu;
            mu_s[rr] = mu;
            rs_s[rr] = rsqrtf(var + 1e-5f);
        }
    }
    __syncthreads();

    const float gm = gamma[h], bt = beta[h];
    #pragma unroll
    for (int r = 0; r < ER; ++r)
        out[(size_t)(r0 + r) * H_DIM + h] = (xs[r][h] - mu_s[r]) * rs_s[r] * gm + bt;
}

// ---------------- launch ----------------------------------------------------
extern "C" void kernel_launch(void* const* d_in, const int* in_sizes, int n_in,
                              void* d_out, int out_size) {
    const float* embeddings = (const float*)d_in[0];
    const float* s0         = (const float*)d_in[1];
    const float* rules      = (const float*)d_in[2];
    const float* W          = (const float*)d_in[3];
    const float* b          = (const float*)d_in[4];
    const float* alpha      = (const float*)d_in[5];
    const float* gamma      = (const float*)d_in[6];
    const float* beta       = (const float*)d_in[7];
    float* out = (float*)d_out;
    (void)in_sizes; (void)n_in; (void)out_size;

    cudaFuncSetAttribute(sims_topk_kernel,
                         cudaFuncAttributeMaxDynamicSharedMemorySize,
                         (int)sizeof(SimsSmem));

    prep_all_kernel<<<(N_PAD + B_ROWS) / 8, 256>>>(rules, embeddings);
    sims_topk_kernel<<<(B_ROWS / BM) * 2, NTHREADS, sizeof(SimsSmem)>>>();
    epilogue_kernel<<<B_ROWS / ER, 256>>>(s0, rules, W, b, alpha, gamma, beta, out);
}